// round 17
// baseline (speedup 1.0000x reference)
#include <cuda_runtime.h>

// pre_spikes [8,1,8192] f32, W [8192,8192] f32, thr [8,1,8192] f32,
// const_inp [8,1,8192] f32 -> out [8,1,8192] f32.
#define BB     8
#define MM     8192
#define NN     8192
#define KSPLIT 64
#define K_TILE (MM / KSPLIT)      // 128
#define TPB    64
#define VEC    4
#define NCOLS  (TPB * VEC)        // 256 columns per block
#define NTILES (NN / NCOLS)       // 32
#define PREF   16                 // W rows prefetched into registers per stage
#define SPIKE_CAP 0.9f

typedef unsigned long long ull;

// L2-resident accumulator [B][N] = 256 KB. Zero at load; the finishing block
// of each N-tile re-zeroes its slice every call (graph-replay invariant).
__device__ float g_accum[(size_t)BB * NN];
// Per-N-tile arrival counters (reset by the finishing block).
__device__ unsigned int g_count[NTILES];

// Packed f32x2 FMA (Blackwell): d = a*b + c on both 32-bit halves.
__device__ __forceinline__ void fma2(ull& d, ull a, ull b, ull c) {
    asm("fma.rn.f32x2 %0, %1, %2, %3;" : "=l"(d) : "l"(a), "l"(b), "l"(c));
}

// 16B streaming load (evict-first in L2): W is read exactly once.
__device__ __forceinline__ void ldcs_v2u64(ull& x, ull& y, const void* p) {
    asm("ld.global.cs.v2.u64 {%0, %1}, [%2];" : "=l"(x), "=l"(y) : "l"(p));
}

// 16B vector reduction into global (sm_90+): one L2 atomic op per 4 floats.
__device__ __forceinline__ void redg_v4f32(float* p, ull lo, ull hi) {
    const float2 a = *reinterpret_cast<const float2*>(&lo);
    const float2 b = *reinterpret_cast<const float2*>(&hi);
    asm volatile("red.global.add.v4.f32 [%0], {%1, %2, %3, %4};"
                 :: "l"(p), "f"(a.x), "f"(a.y), "f"(b.x), "f"(b.y)
                 : "memory");
}

__global__ __launch_bounds__(TPB)
void snn_fused(const float* __restrict__ pre,
               const float* __restrict__ W,
               const float* __restrict__ thr,
               const float* __restrict__ cinp,
               float* __restrict__ out)
{
    // Pre-spike chunk, each amplitude splatted into both halves of an f32x2.
    __shared__ ull sp2[K_TILE][BB];
    __shared__ bool s_last;

    // ks varies FASTEST across bids: a tile's 64 blocks are consecutive ->
    // early tiles finish inside wave 1 and their epilogues hide under the
    // remaining tiles' mainloops instead of piling into the kernel tail.
    const int ks = blockIdx.x;
    const int tile = blockIdx.y;
    const int k0 = ks * K_TILE;
    const int n0 = tile * NCOLS + threadIdx.x * VEC;

    for (int i = threadIdx.x; i < K_TILE * BB; i += TPB) {
        const int b = i >> 7;           // i / K_TILE (K_TILE = 128)
        const int m = i & (K_TILE - 1);
        const float p = pre[(size_t)b * MM + k0 + m];
        ull pk;
        asm("mov.b64 %0, {%1, %1};" : "=l"(pk) : "f"(p));
        sp2[m][b] = pk;
    }
    __syncthreads();

    // 8 batches x 4 columns = 16 f32x2 accumulators.
    ull acc[BB][2];
#pragma unroll
    for (int b = 0; b < BB; b++) { acc[b][0] = 0ULL; acc[b][1] = 0ULL; }

    const char* wbase = reinterpret_cast<const char*>(W + (size_t)k0 * NN + n0);

    // Two-phase inner loop: front-batch PREF independent LDG.128 (MLP=16),
    // then consume with broadcast LDS + FFMA2.
    for (int mb = 0; mb < K_TILE; mb += PREF) {
        ull wx[PREF], wy[PREF];
#pragma unroll
        for (int j = 0; j < PREF; j++) {
            ldcs_v2u64(wx[j], wy[j],
                       wbase + (size_t)(mb + j) * (NN * 4));
        }
#pragma unroll
        for (int j = 0; j < PREF; j++) {
            const ulonglong2* pv =
                reinterpret_cast<const ulonglong2*>(&sp2[mb + j][0]);
            const ulonglong2 p01 = pv[0];
            const ulonglong2 p23 = pv[1];
            const ulonglong2 p45 = pv[2];
            const ulonglong2 p67 = pv[3];
            const ull xw = wx[j], yw = wy[j];
            fma2(acc[0][0], p01.x, xw, acc[0][0]); fma2(acc[0][1], p01.x, yw, acc[0][1]);
            fma2(acc[1][0], p01.y, xw, acc[1][0]); fma2(acc[1][1], p01.y, yw, acc[1][1]);
            fma2(acc[2][0], p23.x, xw, acc[2][0]); fma2(acc[2][1], p23.x, yw, acc[2][1]);
            fma2(acc[3][0], p23.y, xw, acc[3][0]); fma2(acc[3][1], p23.y, yw, acc[3][1]);
            fma2(acc[4][0], p45.x, xw, acc[4][0]); fma2(acc[4][1], p45.x, yw, acc[4][1]);
            fma2(acc[5][0], p45.y, xw, acc[5][0]); fma2(acc[5][1], p45.y, yw, acc[5][1]);
            fma2(acc[6][0], p67.x, xw, acc[6][0]); fma2(acc[6][1], p67.x, yw, acc[6][1]);
            fma2(acc[7][0], p67.y, xw, acc[7][0]); fma2(acc[7][1], p67.y, yw, acc[7][1]);
        }
    }

    // Accumulate partials into the L2-resident accumulator.
#pragma unroll
    for (int b = 0; b < BB; b++) {
        redg_v4f32(&g_accum[(size_t)b * NN + n0], acc[b][0], acc[b][1]);
    }

    // ---- Arrival protocol (threadfence-reduction pattern) ----
    __threadfence();            // make this thread's REDs globally visible
    __syncthreads();            // all threads' REDs+fences precede the bump
    if (threadIdx.x == 0) {
        const unsigned int prev = atomicAdd(&g_count[tile], 1u);
        s_last = (prev == KSPLIT - 1);
    }
    __syncthreads();
    if (!s_last) return;

    // ---- Last block of this N-tile: epilogue for 8 batches x 256 columns ----
    __threadfence();            // acquire: see all other blocks' REDs

    const int nb = tile * NCOLS;
    // 2048 elements = 512 float4; 8 float4 per thread.
#pragma unroll
    for (int v = 0; v < 8; v++) {
        const int e = (v * TPB + threadIdx.x) * VEC;   // 0..2047, vec-aligned
        const int b = e >> 8;                          // e / NCOLS
        const int n = nb + (e & (NCOLS - 1));
        const size_t idx = (size_t)b * NN + n;

        float4 s = *reinterpret_cast<const float4*>(&g_accum[idx]);
        const float4 c = *reinterpret_cast<const float4*>(&cinp[idx]);
        const float4 t = *reinterpret_cast<const float4*>(&thr[idx]);
        s.x = fminf(fmaxf(s.x + c.x - t.x, 0.f), SPIKE_CAP);
        s.y = fminf(fmaxf(s.y + c.y - t.y, 0.f), SPIKE_CAP);
        s.z = fminf(fmaxf(s.z + c.z - t.z, 0.f), SPIKE_CAP);
        s.w = fminf(fmaxf(s.w + c.w - t.w, 0.f), SPIKE_CAP);
        *reinterpret_cast<float4*>(&out[idx]) = s;

        // Restore the zero invariant for the next graph replay.
        *reinterpret_cast<float4*>(&g_accum[idx]) =
            make_float4(0.f, 0.f, 0.f, 0.f);
    }
    if (threadIdx.x == 0) g_count[tile] = 0u;   // reset counter for next call
}

extern "C" void kernel_launch(void* const* d_in, const int* in_sizes, int n_in,
                              void* d_out, int out_size)
{
    const float* pre  = (const float*)d_in[0];  // pre_spikes [8,1,8192]
    const float* W    = (const float*)d_in[1];  // W [8192,8192]
    const float* thr  = (const float*)d_in[2];  // thr [8,1,8192]
    const float* cinp = (const float*)d_in[3];  // const_inp [8,1,8192]
    float* out = (float*)d_out;

    dim3 grid(KSPLIT, NTILES);                  // 64 x 32 = 2048 blocks
    snn_fused<<<grid, TPB>>>(pre, W, thr, cinp, out);
}